// round 1
// baseline (speedup 1.0000x reference)
#include <cuda_runtime.h>
#include <cstdint>

#define BATCH 8
#define SEQ   2048
#define DM    1024
#define DKK   1024

// d_out layout: [output (B,L,DK)] then [attention (B,L,L)]
#define OUT_ATT_OFF ((size_t)BATCH * SEQ * DKK)

// Scratch for Q, K, V projections (allocation-free: __device__ globals)
__device__ float g_q[(size_t)BATCH * SEQ * DKK];
__device__ float g_k[(size_t)BATCH * SEQ * DKK];
__device__ float g_v[(size_t)BATCH * SEQ * DKK];

// ---------------------------------------------------------------------------
// Kernel 1: QKV projection.  C = src @ W^T + bias   (NT GEMM)
//   src: (16384, 1024) row-major, W: (1024, 1024) row-major (out, in)
//   blockIdx.z in {0,1,2} selects {Q,K,V}
// ---------------------------------------------------------------------------
__global__ __launch_bounds__(256)
void qkv_gemm(const float* __restrict__ src,
              const float* __restrict__ Wq, const float* __restrict__ bq,
              const float* __restrict__ Wk, const float* __restrict__ bk,
              const float* __restrict__ Wv, const float* __restrict__ bv)
{
    const float* W;  const float* bias;  float* C;
    if (blockIdx.z == 0)      { W = Wq; bias = bq; C = g_q; }
    else if (blockIdx.z == 1) { W = Wk; bias = bk; C = g_k; }
    else                      { W = Wv; bias = bv; C = g_v; }

    __shared__ float As[16][132];
    __shared__ float Bs[16][132];

    const int tid  = threadIdx.x;
    const int row0 = blockIdx.y * 128;
    const int col0 = blockIdx.x * 128;
    const int ty   = tid >> 4;     // 0..15
    const int tx   = tid & 15;     // 0..15

    const int r  = tid >> 2;       // 0..63
    const int c4 = (tid & 3) * 4;  // 0,4,8,12

    float acc[8][8];
    #pragma unroll
    for (int i = 0; i < 8; i++)
        #pragma unroll
        for (int j = 0; j < 8; j++) acc[i][j] = 0.f;

    for (int k0 = 0; k0 < DM; k0 += 16) {
        float4 a0 = *(const float4*)(src + (size_t)(row0 + r)      * DM + k0 + c4);
        float4 a1 = *(const float4*)(src + (size_t)(row0 + r + 64) * DM + k0 + c4);
        float4 b0 = *(const float4*)(W   + (size_t)(col0 + r)      * DM + k0 + c4);
        float4 b1 = *(const float4*)(W   + (size_t)(col0 + r + 64) * DM + k0 + c4);

        As[c4+0][r]    = a0.x; As[c4+1][r]    = a0.y; As[c4+2][r]    = a0.z; As[c4+3][r]    = a0.w;
        As[c4+0][r+64] = a1.x; As[c4+1][r+64] = a1.y; As[c4+2][r+64] = a1.z; As[c4+3][r+64] = a1.w;
        Bs[c4+0][r]    = b0.x; Bs[c4+1][r]    = b0.y; Bs[c4+2][r]    = b0.z; Bs[c4+3][r]    = b0.w;
        Bs[c4+0][r+64] = b1.x; Bs[c4+1][r+64] = b1.y; Bs[c4+2][r+64] = b1.z; Bs[c4+3][r+64] = b1.w;
        __syncthreads();

        #pragma unroll
        for (int kk = 0; kk < 16; kk++) {
            float a[8], b[8];
            *(float4*)&a[0] = *(const float4*)&As[kk][ty*8];
            *(float4*)&a[4] = *(const float4*)&As[kk][ty*8+4];
            *(float4*)&b[0] = *(const float4*)&Bs[kk][tx*8];
            *(float4*)&b[4] = *(const float4*)&Bs[kk][tx*8+4];
            #pragma unroll
            for (int i = 0; i < 8; i++)
                #pragma unroll
                for (int j = 0; j < 8; j++)
                    acc[i][j] += a[i] * b[j];
        }
        __syncthreads();
    }

    #pragma unroll
    for (int i = 0; i < 8; i++) {
        const int row = row0 + ty*8 + i;
        float* Crow = C + (size_t)row * DKK + col0 + tx*8;
        #pragma unroll
        for (int j = 0; j < 8; j++)
            Crow[j] = acc[i][j] + bias[col0 + tx*8 + j];
    }
}

// ---------------------------------------------------------------------------
// Kernel 2: scores S[b,l,m] = (q_l . k_m) / 32  — lower-triangle tiles only.
//   NT GEMM per batch, written into d_out attention region.
// ---------------------------------------------------------------------------
__global__ __launch_bounds__(256)
void score_gemm(float* __restrict__ att)
{
    const int bx = blockIdx.x;   // m tile
    const int by = blockIdx.y;   // l tile
    if (bx > by) return;         // fully masked tile: never read by softmax

    const int b = blockIdx.z;
    const float* Q = g_q + (size_t)b * SEQ * DKK;
    const float* K = g_k + (size_t)b * SEQ * DKK;
    float*       C = att + (size_t)b * SEQ * SEQ;

    __shared__ float As[16][132];
    __shared__ float Bs[16][132];

    const int tid  = threadIdx.x;
    const int row0 = by * 128;
    const int col0 = bx * 128;
    const int ty   = tid >> 4;
    const int tx   = tid & 15;
    const int r    = tid >> 2;
    const int c4   = (tid & 3) * 4;

    float acc[8][8];
    #pragma unroll
    for (int i = 0; i < 8; i++)
        #pragma unroll
        for (int j = 0; j < 8; j++) acc[i][j] = 0.f;

    for (int k0 = 0; k0 < DKK; k0 += 16) {
        float4 a0 = *(const float4*)(Q + (size_t)(row0 + r)      * DKK + k0 + c4);
        float4 a1 = *(const float4*)(Q + (size_t)(row0 + r + 64) * DKK + k0 + c4);
        float4 b0 = *(const float4*)(K + (size_t)(col0 + r)      * DKK + k0 + c4);
        float4 b1 = *(const float4*)(K + (size_t)(col0 + r + 64) * DKK + k0 + c4);

        As[c4+0][r]    = a0.x; As[c4+1][r]    = a0.y; As[c4+2][r]    = a0.z; As[c4+3][r]    = a0.w;
        As[c4+0][r+64] = a1.x; As[c4+1][r+64] = a1.y; As[c4+2][r+64] = a1.z; As[c4+3][r+64] = a1.w;
        Bs[c4+0][r]    = b0.x; Bs[c4+1][r]    = b0.y; Bs[c4+2][r]    = b0.z; Bs[c4+3][r]    = b0.w;
        Bs[c4+0][r+64] = b1.x; Bs[c4+1][r+64] = b1.y; Bs[c4+2][r+64] = b1.z; Bs[c4+3][r+64] = b1.w;
        __syncthreads();

        #pragma unroll
        for (int kk = 0; kk < 16; kk++) {
            float a[8], b[8];
            *(float4*)&a[0] = *(const float4*)&As[kk][ty*8];
            *(float4*)&a[4] = *(const float4*)&As[kk][ty*8+4];
            *(float4*)&b[0] = *(const float4*)&Bs[kk][tx*8];
            *(float4*)&b[4] = *(const float4*)&Bs[kk][tx*8+4];
            #pragma unroll
            for (int i = 0; i < 8; i++)
                #pragma unroll
                for (int j = 0; j < 8; j++)
                    acc[i][j] += a[i] * b[j];
        }
        __syncthreads();
    }

    #pragma unroll
    for (int i = 0; i < 8; i++) {
        const int row = row0 + ty*8 + i;
        float* Crow = C + (size_t)row * SEQ + col0 + tx*8;
        #pragma unroll
        for (int j = 0; j < 8; j++)
            Crow[j] = acc[i][j] * 0.03125f;   // 1/sqrt(1024)
    }
}

// ---------------------------------------------------------------------------
// Kernel 3: column softmax (softmax over axis=1 == the l/query axis).
//   Column m is valid for rows l >= m (causal).  In-place on att region.
//   Block: 256 threads = 8 row-lanes x 32 columns.  Grid: (SEQ/32, BATCH)
// ---------------------------------------------------------------------------
__global__ __launch_bounds__(256)
void col_softmax(float* __restrict__ att)
{
    const int b  = blockIdx.y;
    const int m0 = blockIdx.x * 32;
    const int tx = threadIdx.x & 31;   // column within group
    const int ty = threadIdx.x >> 5;   // 0..7 row-lane
    const int m  = m0 + tx;

    float* S = att + (size_t)b * SEQ * SEQ;

    // Pass 1: online max + sum over valid rows (l >= m)
    float mx = -INFINITY, sum = 0.f;
    for (int l = m0 + ty; l < SEQ; l += 8) {
        if (l >= m) {
            float x = S[(size_t)l * SEQ + m];
            float mn = fmaxf(mx, x);
            sum = sum * __expf(mx - mn) + __expf(x - mn);
            mx = mn;
        }
    }

    __shared__ float smx[8][33];
    __shared__ float ssm[8][33];
    smx[ty][tx] = mx;
    ssm[ty][tx] = sum;
    __syncthreads();

    if (ty == 0) {
        float M = -INFINITY, Ssum = 0.f;
        #pragma unroll
        for (int i = 0; i < 8; i++) {
            float m2 = smx[i][tx], s2 = ssm[i][tx];
            if (m2 > -INFINITY) {
                float Mn = fmaxf(M, m2);
                Ssum = Ssum * __expf(M - Mn) + s2 * __expf(m2 - Mn);
                M = Mn;
            }
        }
        smx[0][tx] = M;
        ssm[0][tx] = 1.0f / Ssum;
    }
    __syncthreads();

    const float M   = smx[0][tx];
    const float inv = ssm[0][tx];

    // Pass 2: write normalized attention; exact 0 above the diagonal.
    for (int l = ty; l < SEQ; l += 8) {
        size_t idx = (size_t)l * SEQ + m;
        float out = 0.f;
        if (l >= m) out = __expf(S[idx] - M) * inv;
        S[idx] = out;
    }
}

// ---------------------------------------------------------------------------
// Kernel 4: output = attention @ V   (NN GEMM per batch, triangular K-loop)
//   A is lower-triangular (zeros above diagonal), so K-loop stops at row0+128.
// ---------------------------------------------------------------------------
__global__ __launch_bounds__(256)
void out_gemm(const float* __restrict__ att, float* __restrict__ out)
{
    const int b = blockIdx.z;
    const float* A = att + (size_t)b * SEQ * SEQ;
    const float* V = g_v + (size_t)b * SEQ * DKK;
    float*       C = out + (size_t)b * SEQ * DKK;

    __shared__ float As[16][132];
    __shared__ float Bs[16][128];

    const int tid  = threadIdx.x;
    const int row0 = blockIdx.y * 128;
    const int col0 = blockIdx.x * 128;
    const int ty   = tid >> 4;
    const int tx   = tid & 15;

    const int ra   = tid >> 2;         // A-tile row 0..63
    const int ca4  = (tid & 3) * 4;
    const int rb   = tid >> 5;         // B-tile row 0..7
    const int cb4  = (tid & 31) * 4;

    const int kmax = row0 + 128;       // only m < row0+128 can be nonzero

    float acc[8][8];
    #pragma unroll
    for (int i = 0; i < 8; i++)
        #pragma unroll
        for (int j = 0; j < 8; j++) acc[i][j] = 0.f;

    for (int k0 = 0; k0 < kmax; k0 += 16) {
        float4 a0 = *(const float4*)(A + (size_t)(row0 + ra)      * SEQ + k0 + ca4);
        float4 a1 = *(const float4*)(A + (size_t)(row0 + ra + 64) * SEQ + k0 + ca4);
        float4 b0 = *(const float4*)(V + (size_t)(k0 + rb)     * DKK + col0 + cb4);
        float4 b1 = *(const float4*)(V + (size_t)(k0 + rb + 8) * DKK + col0 + cb4);

        As[ca4+0][ra]    = a0.x; As[ca4+1][ra]    = a0.y; As[ca4+2][ra]    = a0.z; As[ca4+3][ra]    = a0.w;
        As[ca4+0][ra+64] = a1.x; As[ca4+1][ra+64] = a1.y; As[ca4+2][ra+64] = a1.z; As[ca4+3][ra+64] = a1.w;
        *(float4*)&Bs[rb][cb4]     = b0;
        *(float4*)&Bs[rb + 8][cb4] = b1;
        __syncthreads();

        #pragma unroll
        for (int kk = 0; kk < 16; kk++) {
            float a[8], bb[8];
            *(float4*)&a[0]  = *(const float4*)&As[kk][ty*8];
            *(float4*)&a[4]  = *(const float4*)&As[kk][ty*8+4];
            *(float4*)&bb[0] = *(const float4*)&Bs[kk][tx*8];
            *(float4*)&bb[4] = *(const float4*)&Bs[kk][tx*8+4];
            #pragma unroll
            for (int i = 0; i < 8; i++)
                #pragma unroll
                for (int j = 0; j < 8; j++)
                    acc[i][j] += a[i] * bb[j];
        }
        __syncthreads();
    }

    #pragma unroll
    for (int i = 0; i < 8; i++) {
        const int row = row0 + ty*8 + i;
        float* Crow = C + (size_t)row * DKK + col0 + tx*8;
        #pragma unroll
        for (int j = 0; j < 8; j++)
            Crow[j] = acc[i][j];
    }
}

// ---------------------------------------------------------------------------
extern "C" void kernel_launch(void* const* d_in, const int* in_sizes, int n_in,
                              void* d_out, int out_size)
{
    const float* src = (const float*)d_in[0];
    const float* Wq  = (const float*)d_in[1];
    const float* bq  = (const float*)d_in[2];
    const float* Wk  = (const float*)d_in[3];
    const float* bk  = (const float*)d_in[4];
    const float* Wv  = (const float*)d_in[5];
    const float* bv  = (const float*)d_in[6];
    // d_in[7] = mask (always 1 in this problem's setup: causal)

    float* out = (float*)d_out;
    float* att = out + OUT_ATT_OFF;

    dim3 g1(DKK / 128, (BATCH * SEQ) / 128, 3);
    qkv_gemm<<<g1, 256>>>(src, Wq, bq, Wk, bk, Wv, bv);

    dim3 g2(SEQ / 128, SEQ / 128, BATCH);
    score_gemm<<<g2, 256>>>(att);

    dim3 g3(SEQ / 32, BATCH);
    col_softmax<<<g3, 256>>>(att);

    dim3 g4(DKK / 128, SEQ / 128, BATCH);
    out_gemm<<<g4, 256>>>(att, out);
}

// round 3
// speedup vs baseline: 3.0571x; 3.0571x over previous
#include <cuda_runtime.h>
#include <cstdint>

#define BATCH 8
#define SEQ   2048
#define DM    1024
#define DKV   1024
#define OUT_ATT_OFF ((size_t)BATCH * SEQ * DKV)

// ---- scratch (__device__ globals: allocation-free) ----
__device__ float g_src[(size_t)BATCH * SEQ * DM];   // tf32-rounded source
__device__ float g_wq[DKV * DM];
__device__ float g_wk[DKV * DM];
__device__ float g_wv[DKV * DM];
__device__ float g_q[(size_t)BATCH * SEQ * DKV];
__device__ float g_k[(size_t)BATCH * SEQ * DKV];
__device__ float g_v[(size_t)BATCH * SEQ * DKV];

// ---- tile config ----
#define BM 128
#define BN 256
#define BK 32
#define LDAS 36                    // padded A pitch (floats)
#define LDBS 36                    // padded B pitch for NT kernels
#define LDVS 264                   // padded V pitch ([k][n] layout) for AV kernel
#define NT_STAGE (BM*LDAS + BN*LDBS)      // 13824 floats
#define AV_STAGE (BM*LDAS + BK*LDVS)      // 13056 floats
#define NT_SMEM  (2 * NT_STAGE * 4)       // 110592 B
#define AV_SMEM  (2 * AV_STAGE * 4)       // 104448 B

// ---------------------------------------------------------------------------
// helpers
// ---------------------------------------------------------------------------
__device__ __forceinline__ float tf32r(float x) {
    uint32_t u;
    asm("cvt.rna.tf32.f32 %0, %1;" : "=r"(u) : "f"(x));
    return __uint_as_float(u);
}
__device__ __forceinline__ uint32_t tf32u(uint32_t x) {
    uint32_t u;
    asm("cvt.rna.tf32.f32 %0, %1;" : "=r"(u) : "f"(__uint_as_float(x)));
    return u;
}
__device__ __forceinline__ uint32_t cvta_s(const void* p) {
    return (uint32_t)__cvta_generic_to_shared(p);
}
__device__ __forceinline__ void cp16(uint32_t s, const void* g) {
    asm volatile("cp.async.cg.shared.global [%0], [%1], 16;\n" :: "r"(s), "l"(g));
}
__device__ __forceinline__ void cp_commit() { asm volatile("cp.async.commit_group;\n" ::); }
__device__ __forceinline__ void cp_wait1()  { asm volatile("cp.async.wait_group 1;\n" ::); }
__device__ __forceinline__ void ldsm4(uint32_t& r0, uint32_t& r1, uint32_t& r2, uint32_t& r3,
                                      uint32_t a) {
    asm volatile("ldmatrix.sync.aligned.m8n8.x4.shared.b16 {%0,%1,%2,%3}, [%4];\n"
                 : "=r"(r0), "=r"(r1), "=r"(r2), "=r"(r3) : "r"(a));
}
__device__ __forceinline__ void mma_tf32(float* d, const uint32_t* a, const uint32_t* b) {
    asm volatile(
        "mma.sync.aligned.m16n8k8.row.col.f32.tf32.tf32.f32 "
        "{%0,%1,%2,%3}, {%4,%5,%6,%7}, {%8,%9}, {%0,%1,%2,%3};\n"
        : "+f"(d[0]), "+f"(d[1]), "+f"(d[2]), "+f"(d[3])
        : "r"(a[0]), "r"(a[1]), "r"(a[2]), "r"(a[3]), "r"(b[0]), "r"(b[1]));
}

// ---------------------------------------------------------------------------
// Kernel 0: RNA-round src and weights into scratch (single launch)
// ---------------------------------------------------------------------------
__global__ __launch_bounds__(256)
void round_all(const float4* __restrict__ src, const float4* __restrict__ wq,
               const float4* __restrict__ wk, const float4* __restrict__ wv)
{
    const int i = blockIdx.x * 256 + threadIdx.x;
    const int nsrc = (int)((size_t)BATCH * SEQ * DM / 4);
    const int nw   = DKV * DM / 4;
    if (i < nsrc) {
        float4 v = src[i];
        v.x = tf32r(v.x); v.y = tf32r(v.y); v.z = tf32r(v.z); v.w = tf32r(v.w);
        ((float4*)g_src)[i] = v;
    }
    if (i < nw) {
        float4 a = wq[i];
        a.x = tf32r(a.x); a.y = tf32r(a.y); a.z = tf32r(a.z); a.w = tf32r(a.w);
        ((float4*)g_wq)[i] = a;
        float4 b = wk[i];
        b.x = tf32r(b.x); b.y = tf32r(b.y); b.z = tf32r(b.z); b.w = tf32r(b.w);
        ((float4*)g_wk)[i] = b;
        float4 c = wv[i];
        c.x = tf32r(c.x); c.y = tf32r(c.y); c.z = tf32r(c.z); c.w = tf32r(c.w);
        ((float4*)g_wv)[i] = c;
    }
}

// ---------------------------------------------------------------------------
// Kernel 1: QKV projection, NT tf32 tensor GEMM.  C = A @ B^T + bias
// ---------------------------------------------------------------------------
__global__ __launch_bounds__(256)
void qkv_tc(const float* __restrict__ bq, const float* __restrict__ bk,
            const float* __restrict__ bv)
{
    extern __shared__ float sm[];
    const float* A = g_src;
    const float* B; const float* bias; float* C;
    if (blockIdx.z == 0)      { B = g_wq; bias = bq; C = g_q; }
    else if (blockIdx.z == 1) { B = g_wk; bias = bk; C = g_k; }
    else                      { B = g_wv; bias = bv; C = g_v; }

    const int tid = threadIdx.x, lane = tid & 31, warp = tid >> 5;
    const int wm = warp >> 2, wn = warp & 3;
    const int row0 = blockIdx.y * BM;
    const int col0 = blockIdx.x * BN;

    const uint32_t s0 = cvta_s(sm);
    uint32_t smA[2] = { s0, s0 + NT_STAGE * 4 };
    uint32_t smB[2] = { s0 + BM * LDAS * 4, s0 + (NT_STAGE + BM * LDAS) * 4 };

    float acc[4][8][4] = {};

    const int aRow = lane & 15;
    const int aCol = (lane >> 4) * 4;
    const int bRow = (lane & 7) + ((lane >> 4) << 3);
    const int bCol = ((lane >> 3) & 1) * 4;

#define NT_LOAD(k0, s)                                                          \
    {                                                                           \
        _Pragma("unroll")                                                       \
        for (int t = 0; t < 4; t++) {                                           \
            int c = tid + t * 256; int r = c >> 3, sg = (c & 7) * 4;            \
            cp16(smA[s] + (r * LDAS + sg) * 4,                                  \
                 A + (size_t)(row0 + r) * DM + (k0) + sg);                      \
        }                                                                       \
        _Pragma("unroll")                                                       \
        for (int t = 0; t < 8; t++) {                                           \
            int c = tid + t * 256; int r = c >> 3, sg = (c & 7) * 4;            \
            cp16(smB[s] + (r * LDBS + sg) * 4,                                  \
                 B + (size_t)(col0 + r) * DM + (k0) + sg);                      \
        }                                                                       \
    }

    NT_LOAD(0, 0); cp_commit();
    int s = 0;
    for (int k0 = 0; k0 < DM; k0 += BK) {
        if (k0 + BK < DM) NT_LOAD(k0 + BK, s ^ 1);
        cp_commit();
        cp_wait1();
        __syncthreads();
        #pragma unroll
        for (int kk = 0; kk < 4; kk++) {
            uint32_t af[4][4];
            #pragma unroll
            for (int i = 0; i < 4; i++)
                ldsm4(af[i][0], af[i][1], af[i][2], af[i][3],
                      smA[s] + ((wm * 64 + i * 16 + aRow) * LDAS + kk * 8 + aCol) * 4);
            uint32_t bf[8][2];
            #pragma unroll
            for (int jj = 0; jj < 4; jj++)
                ldsm4(bf[2*jj][0], bf[2*jj][1], bf[2*jj+1][0], bf[2*jj+1][1],
                      smB[s] + ((wn * 64 + jj * 16 + bRow) * LDBS + kk * 8 + bCol) * 4);
            #pragma unroll
            for (int i = 0; i < 4; i++)
                #pragma unroll
                for (int j = 0; j < 8; j++)
                    mma_tf32(acc[i][j], af[i], bf[j]);
        }
        __syncthreads();
        s ^= 1;
    }

    #pragma unroll
    for (int i = 0; i < 4; i++) {
        const int rr = row0 + wm * 64 + i * 16 + (lane >> 2);
        #pragma unroll
        for (int j = 0; j < 8; j++) {
            const int cc = col0 + wn * 64 + j * 8 + (lane & 3) * 2;
            const float b0 = bias[cc], b1 = bias[cc + 1];
            float2 v0 = { tf32r(acc[i][j][0] + b0), tf32r(acc[i][j][1] + b1) };
            float2 v1 = { tf32r(acc[i][j][2] + b0), tf32r(acc[i][j][3] + b1) };
            *(float2*)(C + (size_t)rr * DKV + cc)       = v0;
            *(float2*)(C + (size_t)(rr + 8) * DKV + cc) = v1;
        }
    }
#undef NT_LOAD
}

// ---------------------------------------------------------------------------
// Kernel 2: scores = (Q @ K^T) / 32, lower-triangle tiles only (NT tf32)
// ---------------------------------------------------------------------------
__global__ __launch_bounds__(256)
void score_tc(float* __restrict__ att)
{
    if ((int)blockIdx.x * BN > (int)blockIdx.y * BM + (BM - 1)) return;  // fully masked

    extern __shared__ float sm[];
    const int b = blockIdx.z;
    const float* A = g_q + (size_t)b * SEQ * DKV;
    const float* B = g_k + (size_t)b * SEQ * DKV;
    float*       C = att + (size_t)b * SEQ * SEQ;

    const int tid = threadIdx.x, lane = tid & 31, warp = tid >> 5;
    const int wm = warp >> 2, wn = warp & 3;
    const int row0 = blockIdx.y * BM;
    const int col0 = blockIdx.x * BN;

    const uint32_t s0 = cvta_s(sm);
    uint32_t smA[2] = { s0, s0 + NT_STAGE * 4 };
    uint32_t smB[2] = { s0 + BM * LDAS * 4, s0 + (NT_STAGE + BM * LDAS) * 4 };

    float acc[4][8][4] = {};
    const int aRow = lane & 15;
    const int aCol = (lane >> 4) * 4;
    const int bRow = (lane & 7) + ((lane >> 4) << 3);
    const int bCol = ((lane >> 3) & 1) * 4;

#define NT_LOAD(k0, s)                                                          \
    {                                                                           \
        _Pragma("unroll")                                                       \
        for (int t = 0; t < 4; t++) {                                           \
            int c = tid + t * 256; int r = c >> 3, sg = (c & 7) * 4;            \
            cp16(smA[s] + (r * LDAS + sg) * 4,                                  \
                 A + (size_t)(row0 + r) * DKV + (k0) + sg);                     \
        }                                                                       \
        _Pragma("unroll")                                                       \
        for (int t = 0; t < 8; t++) {                                           \
            int c = tid + t * 256; int r = c >> 3, sg = (c & 7) * 4;            \
            cp16(smB[s] + (r * LDBS + sg) * 4,                                  \
                 B + (size_t)(col0 + r) * DKV + (k0) + sg);                     \
        }                                                                       \
    }

    NT_LOAD(0, 0); cp_commit();
    int s = 0;
    for (int k0 = 0; k0 < DKV; k0 += BK) {
        if (k0 + BK < DKV) NT_LOAD(k0 + BK, s ^ 1);
        cp_commit();
        cp_wait1();
        __syncthreads();
        #pragma unroll
        for (int kk = 0; kk < 4; kk++) {
            uint32_t af[4][4];
            #pragma unroll
            for (int i = 0; i < 4; i++)
                ldsm4(af[i][0], af[i][1], af[i][2], af[i][3],
                      smA[s] + ((wm * 64 + i * 16 + aRow) * LDAS + kk * 8 + aCol) * 4);
            uint32_t bf[8][2];
            #pragma unroll
            for (int jj = 0; jj < 4; jj++)
                ldsm4(bf[2*jj][0], bf[2*jj][1], bf[2*jj+1][0], bf[2*jj+1][1],
                      smB[s] + ((wn * 64 + jj * 16 + bRow) * LDBS + kk * 8 + bCol) * 4);
            #pragma unroll
            for (int i = 0; i < 4; i++)
                #pragma unroll
                for (int j = 0; j < 8; j++)
                    mma_tf32(acc[i][j], af[i], bf[j]);
        }
        __syncthreads();
        s ^= 1;
    }

    #pragma unroll
    for (int i = 0; i < 4; i++) {
        const int rr = row0 + wm * 64 + i * 16 + (lane >> 2);
        #pragma unroll
        for (int j = 0; j < 8; j++) {
            const int cc = col0 + wn * 64 + j * 8 + (lane & 3) * 2;
            float2 v0 = { acc[i][j][0] * 0.03125f, acc[i][j][1] * 0.03125f };
            float2 v1 = { acc[i][j][2] * 0.03125f, acc[i][j][3] * 0.03125f };
            *(float2*)(C + (size_t)rr * SEQ + cc)       = v0;
            *(float2*)(C + (size_t)(rr + 8) * SEQ + cc) = v1;
        }
    }
#undef NT_LOAD
}

// ---------------------------------------------------------------------------
// Kernel 3: column softmax (axis=1) with causal validity l >= m.
//   Stores FULL fp32 attention (the AV kernel rounds its fragments itself).
// ---------------------------------------------------------------------------
__global__ __launch_bounds__(256)
void col_softmax(float* __restrict__ att)
{
    const int b  = blockIdx.y;
    const int m0 = blockIdx.x * 32;
    const int tx = threadIdx.x & 31;
    const int ty = threadIdx.x >> 5;
    const int m  = m0 + tx;

    float* S = att + (size_t)b * SEQ * SEQ;

    float mx = -INFINITY, sum = 0.f;
    for (int l = m0 + ty; l < SEQ; l += 8) {
        if (l >= m) {
            float x = S[(size_t)l * SEQ + m];
            float mn = fmaxf(mx, x);
            sum = sum * __expf(mx - mn) + __expf(x - mn);
            mx = mn;
        }
    }

    __shared__ float smx[8][33];
    __shared__ float ssm[8][33];
    smx[ty][tx] = mx;
    ssm[ty][tx] = sum;
    __syncthreads();

    if (ty == 0) {
        float M = -INFINITY, Ssum = 0.f;
        #pragma unroll
        for (int i = 0; i < 8; i++) {
            float m2 = smx[i][tx], s2 = ssm[i][tx];
            if (m2 > -INFINITY) {
                float Mn = fmaxf(M, m2);
                Ssum = Ssum * __expf(M - Mn) + s2 * __expf(m2 - Mn);
                M = Mn;
            }
        }
        smx[0][tx] = M;
        ssm[0][tx] = 1.0f / Ssum;
    }
    __syncthreads();

    const float M   = smx[0][tx];
    const float inv = ssm[0][tx];

    for (int l = ty; l < SEQ; l += 8) {
        size_t idx = (size_t)l * SEQ + m;
        float out = 0.f;
        if (l >= m) out = __expf(S[idx] - M) * inv;
        S[idx] = out;
    }
}

// ---------------------------------------------------------------------------
// Kernel 4: output = attention @ V  (NN tf32, truncated triangular K-loop)
//   A fragments RNA-rounded in-register after ldmatrix.
// ---------------------------------------------------------------------------
__global__ __launch_bounds__(256)
void av_tc(const float* __restrict__ att, float* __restrict__ out)
{
    extern __shared__ float sm[];
    const int b = blockIdx.z;
    const float* A = att + (size_t)b * SEQ * SEQ;
    const float* V = g_v + (size_t)b * SEQ * DKV;
    float*       C = out + (size_t)b * SEQ * DKV;

    const int tid = threadIdx.x, lane = tid & 31, warp = tid >> 5;
    const int wm = warp >> 2, wn = warp & 3;
    const int row0 = blockIdx.y * BM;
    const int col0 = blockIdx.x * BN;

    const uint32_t s0 = cvta_s(sm);
    uint32_t smA[2] = { s0, s0 + AV_STAGE * 4 };
    uint32_t smV[2] = { s0 + BM * LDAS * 4, s0 + (AV_STAGE + BM * LDAS) * 4 };

    float acc[4][8][4] = {};
    const int aRow = lane & 15;
    const int aCol = (lane >> 4) * 4;
    const int vK = lane & 3;
    const int vN = lane >> 2;

#define AV_LOAD(k0, s)                                                          \
    {                                                                           \
        _Pragma("unroll")                                                       \
        for (int t = 0; t < 4; t++) {                                           \
            int c = tid + t * 256; int r = c >> 3, sg = (c & 7) * 4;            \
            cp16(smA[s] + (r * LDAS + sg) * 4,                                  \
                 A + (size_t)(row0 + r) * SEQ + (k0) + sg);                     \
        }                                                                       \
        _Pragma("unroll")                                                       \
        for (int t = 0; t < 8; t++) {                                           \
            int c = tid + t * 256; int r = c >> 6, sg = (c & 63) * 4;           \
            cp16(smV[s] + (r * LDVS + sg) * 4,                                  \
                 V + (size_t)((k0) + r) * DKV + col0 + sg);                     \
        }                                                                       \
    }

    const int nch = (blockIdx.y + 1) * (BM / BK);   // K runs to row0+128

    AV_LOAD(0, 0); cp_commit();
    int s = 0;
    for (int ic = 0; ic < nch; ic++) {
        if (ic + 1 < nch) AV_LOAD((ic + 1) * BK, s ^ 1);
        cp_commit();
        cp_wait1();
        __syncthreads();
        const float* Vs = sm + s * AV_STAGE + BM * LDAS;
        #pragma unroll
        for (int kk = 0; kk < 4; kk++) {
            uint32_t af[4][4];
            #pragma unroll
            for (int i = 0; i < 4; i++) {
                ldsm4(af[i][0], af[i][1], af[i][2], af[i][3],
                      smA[s] + ((wm * 64 + i * 16 + aRow) * LDAS + kk * 8 + aCol) * 4);
                af[i][0] = tf32u(af[i][0]); af[i][1] = tf32u(af[i][1]);
                af[i][2] = tf32u(af[i][2]); af[i][3] = tf32u(af[i][3]);
            }
            uint32_t bf[8][2];
            #pragma unroll
            for (int j = 0; j < 8; j++) {
                bf[j][0] = __float_as_uint(Vs[(kk * 8 + vK)     * LDVS + wn * 64 + j * 8 + vN]);
                bf[j][1] = __float_as_uint(Vs[(kk * 8 + vK + 4) * LDVS + wn * 64 + j * 8 + vN]);
            }
            #pragma unroll
            for (int i = 0; i < 4; i++)
                #pragma unroll
                for (int j = 0; j < 8; j++)
                    mma_tf32(acc[i][j], af[i], bf[j]);
        }
        __syncthreads();
        s ^= 1;
    }

    #pragma unroll
    for (int i = 0; i < 4; i++) {
        const int rr = row0 + wm * 64 + i * 16 + (lane >> 2);
        #pragma unroll
        for (int j = 0; j < 8; j++) {
            const int cc = col0 + wn * 64 + j * 8 + (lane & 3) * 2;
            *(float2*)(C + (size_t)rr * DKV + cc)       = make_float2(acc[i][j][0], acc[i][j][1]);
            *(float2*)(C + (size_t)(rr + 8) * DKV + cc) = make_float2(acc[i][j][2], acc[i][j][3]);
        }
    }
#undef AV_LOAD
}

// ---------------------------------------------------------------------------
extern "C" void kernel_launch(void* const* d_in, const int* in_sizes, int n_in,
                              void* d_out, int out_size)
{
    const float* src = (const float*)d_in[0];
    const float* Wq  = (const float*)d_in[1];
    const float* bq  = (const float*)d_in[2];
    const float* Wk  = (const float*)d_in[3];
    const float* bk  = (const float*)d_in[4];
    const float* Wv  = (const float*)d_in[5];
    const float* bv  = (const float*)d_in[6];

    float* out = (float*)d_out;
    float* att = out + OUT_ATT_OFF;

    cudaFuncSetAttribute(qkv_tc,   cudaFuncAttributeMaxDynamicSharedMemorySize, NT_SMEM);
    cudaFuncSetAttribute(score_tc, cudaFuncAttributeMaxDynamicSharedMemorySize, NT_SMEM);
    cudaFuncSetAttribute(av_tc,    cudaFuncAttributeMaxDynamicSharedMemorySize, AV_SMEM);

    {
        int n4 = (int)((size_t)BATCH * SEQ * DM / 4);
        round_all<<<(n4 + 255) / 256, 256>>>((const float4*)src, (const float4*)Wq,
                                             (const float4*)Wk, (const float4*)Wv);
    }
    qkv_tc<<<dim3(DKV / BN, (BATCH * SEQ) / BM, 3), 256, NT_SMEM>>>(bq, bk, bv);
    score_tc<<<dim3(SEQ / BN, SEQ / BM, BATCH), 256, NT_SMEM>>>(att);
    col_softmax<<<dim3(SEQ / 32, BATCH), 256>>>(att);
    av_tc<<<dim3(DKV / BN, SEQ / BM, BATCH), 256, AV_SMEM>>>(att, out);
}